// round 1
// baseline (speedup 1.0000x reference)
#include <cuda_runtime.h>

// Problem constants
#define B_  2
#define S_  2048
#define D_  1024
#define H_  16
#define HD_ 64
#define M_  (B_ * S_)   // 4096 rows of x / attn-out

// Scratch (allocation-free rule: __device__ globals)
// g_qkv laid out [3][B][H][S][hd]  (50.3 MB)
__device__ float g_qkv[3u * B_ * H_ * S_ * HD_];
// g_attn laid out [B][S][H*hd] = [4096][1024]  (16.8 MB)
__device__ float g_attn[(size_t)M_ * D_];

// ----------------------------------------------------------------------------
// Tiled SGEMM with bias:  C[M,N] = A[M,K] @ W[N,K]^T + bias[N]
// BM=BN=128, BK=8, 256 threads, 8x8 micro-tile per thread.
// SCATTER=1: epilogue writes into g_qkv [3][B][H][S][hd] (QKV projection).
// SCATTER=0: writes C row-major (output projection). Ain==nullptr -> g_attn.
// ----------------------------------------------------------------------------
template<int SCATTER>
__global__ __launch_bounds__(256)
void gemm_bias_kernel(const float* __restrict__ Ain,
                      const float* __restrict__ W,
                      const float* __restrict__ bias,
                      float* __restrict__ C,
                      int N, int K)
{
    const float* A = Ain ? Ain : g_attn;

    __shared__ float As[8][128];
    __shared__ float Bs[8][128];

    const int tid = threadIdx.x;
    const int tx  = tid & 15;    // 0..15 -> output cols tx*8..+8
    const int ty  = tid >> 4;    // 0..15 -> output rows ty*8..+8
    const int m0  = blockIdx.y * 128;
    const int n0  = blockIdx.x * 128;

    const int lr = tid >> 1;         // 0..127: row loaded by this thread
    const int lc = (tid & 1) * 4;    // 0 or 4: k-offset (float4)

    float acc[8][8];
#pragma unroll
    for (int i = 0; i < 8; i++)
#pragma unroll
        for (int j = 0; j < 8; j++) acc[i][j] = 0.0f;

    const float* aptr = A + (size_t)(m0 + lr) * K + lc;
    const float* wptr = W + (size_t)(n0 + lr) * K + lc;

    for (int k0 = 0; k0 < K; k0 += 8) {
        float4 av = *(const float4*)(aptr + k0);
        float4 wv = *(const float4*)(wptr + k0);
        __syncthreads();   // previous iteration's consumers done
        As[lc + 0][lr] = av.x; As[lc + 1][lr] = av.y;
        As[lc + 2][lr] = av.z; As[lc + 3][lr] = av.w;
        Bs[lc + 0][lr] = wv.x; Bs[lc + 1][lr] = wv.y;
        Bs[lc + 2][lr] = wv.z; Bs[lc + 3][lr] = wv.w;
        __syncthreads();

#pragma unroll
        for (int kk = 0; kk < 8; kk++) {
            float a[8], b[8];
#pragma unroll
            for (int i = 0; i < 8; i++) a[i] = As[kk][ty * 8 + i];
#pragma unroll
            for (int j = 0; j < 8; j++) b[j] = Bs[kk][tx * 8 + j];
#pragma unroll
            for (int i = 0; i < 8; i++)
#pragma unroll
                for (int j = 0; j < 8; j++)
                    acc[i][j] = fmaf(a[i], b[j], acc[i][j]);
        }
    }

#pragma unroll
    for (int i = 0; i < 8; i++) {
        const int m = m0 + ty * 8 + i;
#pragma unroll
        for (int j = 0; j < 8; j++) {
            const int n = n0 + tx * 8 + j;
            const float v = acc[i][j] + bias[n];
            if (SCATTER) {
                // n decomposes as (three, h, d); m as (b, s)
                const int three = n >> 10;           // /1024
                const int h     = (n >> 6) & (H_ - 1);
                const int d     = n & (HD_ - 1);
                const int b     = m >> 11;           // /2048
                const int s     = m & (S_ - 1);
                g_qkv[((size_t)three * (B_ * H_) + b * H_ + h) * (S_ * HD_)
                      + (size_t)s * HD_ + d] = v;
            } else {
                C[(size_t)m * N + n] = v;
            }
        }
    }
}

// ----------------------------------------------------------------------------
// Flash attention: 1 thread = 1 query row. Block = 64 queries of one (b,h).
// K/V streamed through smem in 32-key tiles; online softmax.
// gridDim = (S/64, B*H), blockDim = 64.
// ----------------------------------------------------------------------------
__global__ __launch_bounds__(64)
void attn_kernel()
{
    const int bh    = blockIdx.y;                     // b*H + h
    const int q_idx = blockIdx.x * 64 + threadIdx.x;  // query position in S

    const float* Qp = g_qkv + (size_t)bh * (S_ * HD_) + (size_t)q_idx * HD_;
    const float* Kp = g_qkv + (size_t)(B_ * H_ + bh) * (S_ * HD_);
    const float* Vp = g_qkv + (size_t)(2 * B_ * H_ + bh) * (S_ * HD_);

    __shared__ float4 Ksh[32][16];
    __shared__ float4 Vsh[32][16];

    const float scale = 0.125f;   // 1/sqrt(64)
    float4 q[16];
#pragma unroll
    for (int c = 0; c < 16; c++) {
        float4 t = ((const float4*)Qp)[c];
        q[c] = make_float4(t.x * scale, t.y * scale, t.z * scale, t.w * scale);
    }

    float4 acc[16];
#pragma unroll
    for (int c = 0; c < 16; c++) acc[c] = make_float4(0.f, 0.f, 0.f, 0.f);
    float mrow = -3.0e38f;
    float lrow = 0.0f;

    for (int kt = 0; kt < S_; kt += 32) {
        __syncthreads();
        // load 32x64 K and V tiles: 512 float4 each, 64 threads -> 8 apiece
#pragma unroll
        for (int i = 0; i < 8; i++) {
            const int idx = threadIdx.x + i * 64;   // 0..511
            const int r = idx >> 4, c = idx & 15;
            Ksh[r][c] = ((const float4*)(Kp + (size_t)(kt + r) * HD_))[c];
            Vsh[r][c] = ((const float4*)(Vp + (size_t)(kt + r) * HD_))[c];
        }
        __syncthreads();

        float s[32];
#pragma unroll
        for (int j = 0; j < 32; j++) {
            float4 p = make_float4(0.f, 0.f, 0.f, 0.f);
#pragma unroll
            for (int c = 0; c < 16; c++) {
                const float4 kv = Ksh[j][c];       // broadcast across threads
                p.x = fmaf(q[c].x, kv.x, p.x);
                p.y = fmaf(q[c].y, kv.y, p.y);
                p.z = fmaf(q[c].z, kv.z, p.z);
                p.w = fmaf(q[c].w, kv.w, p.w);
            }
            s[j] = (p.x + p.y) + (p.z + p.w);
        }

        float mt = s[0];
#pragma unroll
        for (int j = 1; j < 32; j++) mt = fmaxf(mt, s[j]);
        const float m_new = fmaxf(mrow, mt);
        const float alpha = __expf(mrow - m_new);
        lrow *= alpha;
#pragma unroll
        for (int c = 0; c < 16; c++) {
            acc[c].x *= alpha; acc[c].y *= alpha;
            acc[c].z *= alpha; acc[c].w *= alpha;
        }
        mrow = m_new;

#pragma unroll
        for (int j = 0; j < 32; j++) {
            const float p = __expf(s[j] - mrow);
            lrow += p;
#pragma unroll
            for (int c = 0; c < 16; c++) {
                const float4 vv = Vsh[j][c];
                acc[c].x = fmaf(p, vv.x, acc[c].x);
                acc[c].y = fmaf(p, vv.y, acc[c].y);
                acc[c].z = fmaf(p, vv.z, acc[c].z);
                acc[c].w = fmaf(p, vv.w, acc[c].w);
            }
        }
    }

    const int b = bh >> 4;          // / H_
    const int h = bh & (H_ - 1);
    const float inv = 1.0f / lrow;
    float4* dst = (float4*)(g_attn + (size_t)(b * S_ + q_idx) * D_ + h * HD_);
#pragma unroll
    for (int c = 0; c < 16; c++) {
        dst[c] = make_float4(acc[c].x * inv, acc[c].y * inv,
                             acc[c].z * inv, acc[c].w * inv);
    }
}

// ----------------------------------------------------------------------------
extern "C" void kernel_launch(void* const* d_in, const int* in_sizes, int n_in,
                              void* d_out, int out_size)
{
    const float* x      = (const float*)d_in[0];
    const float* w_qkv  = (const float*)d_in[1];
    const float* b_qkv  = (const float*)d_in[2];
    const float* w_proj = (const float*)d_in[3];
    const float* b_proj = (const float*)d_in[4];
    float* out = (float*)d_out;

    // 1) QKV projection, scattered into [3,B,H,S,hd]
    dim3 g1((3 * D_) / 128, M_ / 128);       // (24, 32)
    gemm_bias_kernel<1><<<g1, 256>>>(x, w_qkv, b_qkv, nullptr, 3 * D_, D_);

    // 2) attention -> g_attn [B,S,D]
    attn_kernel<<<dim3(S_ / 64, B_ * H_), 64>>>();

    // 3) output projection -> d_out
    dim3 g2(D_ / 128, M_ / 128);             // (8, 32)
    gemm_bias_kernel<0><<<g2, 256>>>(nullptr, w_proj, b_proj, out, D_, D_);
}

// round 2
// speedup vs baseline: 3.5086x; 3.5086x over previous
#include <cuda_runtime.h>

// Problem constants
#define B_  2
#define S_  2048
#define D_  1024
#define H_  16
#define HD_ 64
#define M_  (B_ * S_)   // 4096

// Scratch (allocation-free rule: __device__ globals)
__device__ float g_qkv[3u * B_ * H_ * S_ * HD_];   // [3][B][H][S][hd]
__device__ float g_attn[(size_t)M_ * D_];          // [B*S][D]

// ---------------------------------------------------------------------------
// tf32 helpers
// ---------------------------------------------------------------------------
__device__ __forceinline__ unsigned f2tf32(float f) {
    unsigned u;
    asm("cvt.rna.tf32.f32 %0, %1;" : "=r"(u) : "f"(f));
    return u;
}

__device__ __forceinline__ void mma_tf32(float* c, const unsigned* a, const unsigned* b) {
    asm("mma.sync.aligned.m16n8k8.row.col.f32.tf32.tf32.f32 "
        "{%0,%1,%2,%3},{%4,%5,%6,%7},{%8,%9},{%0,%1,%2,%3};"
        : "+f"(c[0]), "+f"(c[1]), "+f"(c[2]), "+f"(c[3])
        : "r"(a[0]), "r"(a[1]), "r"(a[2]), "r"(a[3]), "r"(b[0]), "r"(b[1]));
}

// ---------------------------------------------------------------------------
// Tensor-core GEMM: C[M,N] = A[M,K] @ W[N,K]^T + bias[N]   (tf32, fp32 acc)
// BM=BN=128, BK=16, 256 threads (8 warps: 4 in M x 2 in N), warp tile 32x64.
// SCATTER=1: epilogue writes g_qkv [3][B][H][S][hd]. Ain==nullptr -> g_attn.
// ---------------------------------------------------------------------------
#define BM 128
#define BN 128
#define BK 16
#define LDA 20   // smem row stride (words): 16 + 4 pad -> conflict-free frags

template<int SCATTER>
__global__ __launch_bounds__(256)
void gemm_tc(const float* __restrict__ Ain, const float* __restrict__ W,
             const float* __restrict__ bias, float* __restrict__ C,
             int N, int K)
{
    const float* A = Ain ? Ain : g_attn;

    __shared__ unsigned As[BM * LDA];
    __shared__ unsigned Bs[BN * LDA];

    const int tid  = threadIdx.x;
    const int lane = tid & 31, warp = tid >> 5;
    const int wm = warp & 3, wn = warp >> 2;   // 4 M-warps x 2 N-warps
    const int g  = lane >> 2, tg = lane & 3;
    const int m0 = blockIdx.y * BM, n0 = blockIdx.x * BN;

    // global-load mapping: 512 float4 per tile per matrix, 2 per thread
    const int r0 = tid >> 2;           // 0..63 (and +64)
    const int kq = (tid & 3) * 4;      // 0,4,8,12

    float acc[2][8][4];
#pragma unroll
    for (int mi = 0; mi < 2; mi++)
#pragma unroll
        for (int ni = 0; ni < 8; ni++)
#pragma unroll
            for (int c = 0; c < 4; c++) acc[mi][ni][c] = 0.0f;

    const float* aA = A + (size_t)m0 * K;
    const float* aW = W + (size_t)n0 * K;

    float4 pa0 = *(const float4*)(aA + (size_t)r0 * K + kq);
    float4 pa1 = *(const float4*)(aA + (size_t)(r0 + 64) * K + kq);
    float4 pb0 = *(const float4*)(aW + (size_t)r0 * K + kq);
    float4 pb1 = *(const float4*)(aW + (size_t)(r0 + 64) * K + kq);

    for (int k0 = 0; k0 < K; k0 += BK) {
        __syncthreads();
        *(uint4*)&As[r0 * LDA + kq] =
            make_uint4(f2tf32(pa0.x), f2tf32(pa0.y), f2tf32(pa0.z), f2tf32(pa0.w));
        *(uint4*)&As[(r0 + 64) * LDA + kq] =
            make_uint4(f2tf32(pa1.x), f2tf32(pa1.y), f2tf32(pa1.z), f2tf32(pa1.w));
        *(uint4*)&Bs[r0 * LDA + kq] =
            make_uint4(f2tf32(pb0.x), f2tf32(pb0.y), f2tf32(pb0.z), f2tf32(pb0.w));
        *(uint4*)&Bs[(r0 + 64) * LDA + kq] =
            make_uint4(f2tf32(pb1.x), f2tf32(pb1.y), f2tf32(pb1.z), f2tf32(pb1.w));
        __syncthreads();

        const int kn = k0 + BK;
        if (kn < K) {
            pa0 = *(const float4*)(aA + (size_t)r0 * K + kn + kq);
            pa1 = *(const float4*)(aA + (size_t)(r0 + 64) * K + kn + kq);
            pb0 = *(const float4*)(aW + (size_t)r0 * K + kn + kq);
            pb1 = *(const float4*)(aW + (size_t)(r0 + 64) * K + kn + kq);
        }

#pragma unroll
        for (int ks = 0; ks < 2; ks++) {
            const int kb = ks * 8;
            unsigned af[2][4], bf[8][2];
#pragma unroll
            for (int mi = 0; mi < 2; mi++) {
                const int rb = wm * 32 + mi * 16;
                af[mi][0] = As[(rb + g) * LDA + kb + tg];
                af[mi][1] = As[(rb + 8 + g) * LDA + kb + tg];
                af[mi][2] = As[(rb + g) * LDA + kb + tg + 4];
                af[mi][3] = As[(rb + 8 + g) * LDA + kb + tg + 4];
            }
#pragma unroll
            for (int ni = 0; ni < 8; ni++) {
                const int cb = wn * 64 + ni * 8;
                bf[ni][0] = Bs[(cb + g) * LDA + kb + tg];
                bf[ni][1] = Bs[(cb + g) * LDA + kb + tg + 4];
            }
#pragma unroll
            for (int mi = 0; mi < 2; mi++)
#pragma unroll
                for (int ni = 0; ni < 8; ni++)
                    mma_tf32(acc[mi][ni], af[mi], bf[ni]);
        }
    }

    // epilogue: c0=C[g][2tg], c1=C[g][2tg+1], c2=C[g+8][2tg], c3=C[g+8][2tg+1]
#pragma unroll
    for (int mi = 0; mi < 2; mi++) {
#pragma unroll
        for (int half = 0; half < 2; half++) {
            const int m = m0 + wm * 32 + mi * 16 + g + half * 8;
#pragma unroll
            for (int ni = 0; ni < 8; ni++) {
                const int n = n0 + wn * 64 + ni * 8 + 2 * tg;
                const float v0 = acc[mi][ni][half * 2 + 0] + bias[n];
                const float v1 = acc[mi][ni][half * 2 + 1] + bias[n + 1];
                if (SCATTER) {
                    const int three = n >> 10;
                    const int h = (n >> 6) & (H_ - 1);
                    const int d = n & (HD_ - 1);
                    const int b = m >> 11;
                    const int s = m & (S_ - 1);
                    *(float2*)&g_qkv[((size_t)three * (B_ * H_) + b * H_ + h) * (S_ * HD_)
                                     + (size_t)s * HD_ + d] = make_float2(v0, v1);
                } else {
                    *(float2*)&C[(size_t)m * N + n] = make_float2(v0, v1);
                }
            }
        }
    }
}

// ---------------------------------------------------------------------------
// Tensor-core flash attention. CTA = 64 queries of one (b,h); 4 warps x 16 rows.
// 32-key tiles. tf32 mma for QK^T and PV, fp32 online softmax.
// grid = (S/64, B*H), block = 128.
// ---------------------------------------------------------------------------
#define KST 68   // Ks row stride (words): bank-conflict-free for QK B-frags
#define VST 72   // Vs row stride: conflict-free for PV B-frags
#define PST 36   // Ps row stride: conflict-free for PV A-frags

__global__ __launch_bounds__(128)
void attn_tc()
{
    const int bh   = blockIdx.y;
    const int q0   = blockIdx.x * 64;
    const int tid  = threadIdx.x;
    const int warp = tid >> 5, lane = tid & 31;
    const int g = lane >> 2, tg = lane & 3;
    const int wq = warp * 16;

    const float* Qp = g_qkv + (size_t)bh * (S_ * HD_);
    const float* Kp = g_qkv + (size_t)(B_ * H_ + bh) * (S_ * HD_);
    const float* Vp = g_qkv + (size_t)(2 * B_ * H_ + bh) * (S_ * HD_);

    __shared__ unsigned Ks[32 * KST];
    __shared__ unsigned Vs[32 * VST];
    __shared__ unsigned Ps[4][16 * PST];

    // Q fragments (A, m16 x k64 = 8 k-steps), pre-scaled by 1/sqrt(hd)=0.125
    unsigned qa[8][4];
    {
        const float* Qr0 = Qp + (size_t)(q0 + wq + g) * HD_;
        const float* Qr1 = Qp + (size_t)(q0 + wq + g + 8) * HD_;
#pragma unroll
        for (int ks = 0; ks < 8; ks++) {
            qa[ks][0] = f2tf32(Qr0[ks * 8 + tg] * 0.125f);
            qa[ks][1] = f2tf32(Qr1[ks * 8 + tg] * 0.125f);
            qa[ks][2] = f2tf32(Qr0[ks * 8 + tg + 4] * 0.125f);
            qa[ks][3] = f2tf32(Qr1[ks * 8 + tg + 4] * 0.125f);
        }
    }

    float o[8][4];
#pragma unroll
    for (int ni = 0; ni < 8; ni++)
#pragma unroll
        for (int c = 0; c < 4; c++) o[ni][c] = 0.0f;
    float m0v = -3.0e38f, m1v = -3.0e38f, l0 = 0.0f, l1 = 0.0f;

    for (int kt = 0; kt < S_; kt += 32) {
        __syncthreads();
        // load 32x64 K and V tiles: 512 float4 each, 4 per thread
#pragma unroll
        for (int i = 0; i < 4; i++) {
            const int idx = tid + i * 128;
            const int row = idx >> 4, cq = (idx & 15) * 4;
            float4 kv = *(const float4*)(Kp + (size_t)(kt + row) * HD_ + cq);
            float4 vv = *(const float4*)(Vp + (size_t)(kt + row) * HD_ + cq);
            *(uint4*)&Ks[row * KST + cq] =
                make_uint4(f2tf32(kv.x), f2tf32(kv.y), f2tf32(kv.z), f2tf32(kv.w));
            *(uint4*)&Vs[row * VST + cq] =
                make_uint4(f2tf32(vv.x), f2tf32(vv.y), f2tf32(vv.z), f2tf32(vv.w));
        }
        __syncthreads();

        // S = Q K^T : warp computes m16 x n32, k=64
        float sc[4][4];
#pragma unroll
        for (int ni = 0; ni < 4; ni++)
#pragma unroll
            for (int c = 0; c < 4; c++) sc[ni][c] = 0.0f;
#pragma unroll
        for (int ks = 0; ks < 8; ks++) {
#pragma unroll
            for (int ni = 0; ni < 4; ni++) {
                unsigned bf[2];
                bf[0] = Ks[(ni * 8 + g) * KST + ks * 8 + tg];
                bf[1] = Ks[(ni * 8 + g) * KST + ks * 8 + tg + 4];
                mma_tf32(sc[ni], qa[ks], bf);
            }
        }

        // online softmax (rows g and g+8; 4 lanes per row: shfl xor 1,2)
        float mt0 = -3.0e38f, mt1 = -3.0e38f;
#pragma unroll
        for (int ni = 0; ni < 4; ni++) {
            mt0 = fmaxf(mt0, fmaxf(sc[ni][0], sc[ni][1]));
            mt1 = fmaxf(mt1, fmaxf(sc[ni][2], sc[ni][3]));
        }
        mt0 = fmaxf(mt0, __shfl_xor_sync(0xffffffffu, mt0, 1));
        mt0 = fmaxf(mt0, __shfl_xor_sync(0xffffffffu, mt0, 2));
        mt1 = fmaxf(mt1, __shfl_xor_sync(0xffffffffu, mt1, 1));
        mt1 = fmaxf(mt1, __shfl_xor_sync(0xffffffffu, mt1, 2));

        const float mn0 = fmaxf(m0v, mt0), mn1 = fmaxf(m1v, mt1);
        const float a0 = __expf(m0v - mn0), a1 = __expf(m1v - mn1);
        m0v = mn0; m1v = mn1;
        l0 *= a0; l1 *= a1;
#pragma unroll
        for (int ni = 0; ni < 8; ni++) {
            o[ni][0] *= a0; o[ni][1] *= a0;
            o[ni][2] *= a1; o[ni][3] *= a1;
        }

        float s0 = 0.0f, s1 = 0.0f;
#pragma unroll
        for (int ni = 0; ni < 4; ni++) {
            const float p0 = __expf(sc[ni][0] - mn0);
            const float p1 = __expf(sc[ni][1] - mn0);
            const float p2 = __expf(sc[ni][2] - mn1);
            const float p3 = __expf(sc[ni][3] - mn1);
            s0 += p0 + p1; s1 += p2 + p3;
            *(uint2*)&Ps[warp][g * PST + ni * 8 + 2 * tg] =
                make_uint2(f2tf32(p0), f2tf32(p1));
            *(uint2*)&Ps[warp][(g + 8) * PST + ni * 8 + 2 * tg] =
                make_uint2(f2tf32(p2), f2tf32(p3));
        }
        s0 += __shfl_xor_sync(0xffffffffu, s0, 1);
        s0 += __shfl_xor_sync(0xffffffffu, s0, 2);
        s1 += __shfl_xor_sync(0xffffffffu, s1, 1);
        s1 += __shfl_xor_sync(0xffffffffu, s1, 2);
        l0 += s0; l1 += s1;
        __syncwarp();

        // O += P V : A = P[16][32] (4 k-steps), B = V[32][64] (8 n-tiles)
#pragma unroll
        for (int ks = 0; ks < 4; ks++) {
            unsigned pa[4];
            pa[0] = Ps[warp][g * PST + ks * 8 + tg];
            pa[1] = Ps[warp][(g + 8) * PST + ks * 8 + tg];
            pa[2] = Ps[warp][g * PST + ks * 8 + tg + 4];
            pa[3] = Ps[warp][(g + 8) * PST + ks * 8 + tg + 4];
#pragma unroll
            for (int ni = 0; ni < 8; ni++) {
                unsigned bf[2];
                bf[0] = Vs[(ks * 8 + tg) * VST + ni * 8 + g];
                bf[1] = Vs[(ks * 8 + tg + 4) * VST + ni * 8 + g];
                mma_tf32(o[ni], pa, bf);
            }
        }
    }

    // epilogue: normalize and write to g_attn [B*S][D] at head offset
    const int b = bh >> 4, h = bh & (H_ - 1);
    const float i0 = 1.0f / l0, i1 = 1.0f / l1;
    float* O0 = g_attn + (size_t)(b * S_ + q0 + wq + g) * D_ + h * HD_;
    float* O1 = g_attn + (size_t)(b * S_ + q0 + wq + g + 8) * D_ + h * HD_;
#pragma unroll
    for (int ni = 0; ni < 8; ni++) {
        const int c = ni * 8 + 2 * tg;
        *(float2*)(O0 + c) = make_float2(o[ni][0] * i0, o[ni][1] * i0);
        *(float2*)(O1 + c) = make_float2(o[ni][2] * i1, o[ni][3] * i1);
    }
}

// ---------------------------------------------------------------------------
extern "C" void kernel_launch(void* const* d_in, const int* in_sizes, int n_in,
                              void* d_out, int out_size)
{
    const float* x      = (const float*)d_in[0];
    const float* w_qkv  = (const float*)d_in[1];
    const float* b_qkv  = (const float*)d_in[2];
    const float* w_proj = (const float*)d_in[3];
    const float* b_proj = (const float*)d_in[4];
    float* out = (float*)d_out;

    // 1) QKV projection -> g_qkv [3,B,H,S,hd]
    dim3 g1((3 * D_) / BN, M_ / BM);     // (24, 32)
    gemm_tc<1><<<g1, 256>>>(x, w_qkv, b_qkv, nullptr, 3 * D_, D_);

    // 2) attention -> g_attn [B,S,D]
    attn_tc<<<dim3(S_ / 64, B_ * H_), 128>>>();

    // 3) output projection -> d_out
    dim3 g2(D_ / BN, M_ / BM);           // (8, 32)
    gemm_tc<0><<<g2, 256>>>(nullptr, w_proj, b_proj, out, D_, D_);
}

// round 3
// speedup vs baseline: 7.9094x; 2.2543x over previous
#include <cuda_runtime.h>
#include <cuda_fp16.h>

// Problem constants
#define B_  2
#define S_  2048
#define D_  1024
#define H_  16
#define HD_ 64
#define M_  (B_ * S_)   // 4096

// Scratch (allocation-free rule: __device__ globals)
__device__ __half g_xh[(size_t)M_ * D_];          // x in fp16
__device__ __half g_wqkvh[(size_t)3 * D_ * D_];   // w_qkv in fp16
__device__ __half g_wprojh[(size_t)D_ * D_];      // w_proj in fp16
__device__ __half g_qkvh[(size_t)3 * B_ * H_ * S_ * HD_];  // [3][B][H][S][hd]
__device__ __half g_attnh[(size_t)M_ * D_];       // attention out, fp16

// ---------------------------------------------------------------------------
// helpers
// ---------------------------------------------------------------------------
__device__ __forceinline__ unsigned smem_u32(const void* p) {
    return (unsigned)__cvta_generic_to_shared(p);
}
__device__ __forceinline__ void cp_async16(unsigned dst, const void* src) {
    asm volatile("cp.async.cg.shared.global [%0], [%1], 16;\n" :: "r"(dst), "l"(src));
}
__device__ __forceinline__ void cp_commit() {
    asm volatile("cp.async.commit_group;\n");
}
template<int N>
__device__ __forceinline__ void cp_wait() {
    asm volatile("cp.async.wait_group %0;\n" :: "n"(N));
}
__device__ __forceinline__ void ldsm4(unsigned& r0, unsigned& r1, unsigned& r2,
                                      unsigned& r3, unsigned a) {
    asm volatile("ldmatrix.sync.aligned.m8n8.x4.shared.b16 {%0,%1,%2,%3},[%4];"
                 : "=r"(r0), "=r"(r1), "=r"(r2), "=r"(r3) : "r"(a));
}
__device__ __forceinline__ void ldsm4t(unsigned& r0, unsigned& r1, unsigned& r2,
                                       unsigned& r3, unsigned a) {
    asm volatile("ldmatrix.sync.aligned.m8n8.x4.trans.shared.b16 {%0,%1,%2,%3},[%4];"
                 : "=r"(r0), "=r"(r1), "=r"(r2), "=r"(r3) : "r"(a));
}
__device__ __forceinline__ void mma16816(float* c, const unsigned* a, const unsigned* b) {
    asm volatile("mma.sync.aligned.m16n8k16.row.col.f32.f16.f16.f32 "
                 "{%0,%1,%2,%3},{%4,%5,%6,%7},{%8,%9},{%0,%1,%2,%3};"
                 : "+f"(c[0]), "+f"(c[1]), "+f"(c[2]), "+f"(c[3])
                 : "r"(a[0]), "r"(a[1]), "r"(a[2]), "r"(a[3]), "r"(b[0]), "r"(b[1]));
}

// ---------------------------------------------------------------------------
// fp32 -> fp16 convert (vectorized, one-shot)
// ---------------------------------------------------------------------------
__global__ void cvt_kernel(const float* __restrict__ in, __half* __restrict__ out, int n) {
    int i = (blockIdx.x * blockDim.x + threadIdx.x) * 4;
    if (i < n) {
        float4 v = *(const float4*)(in + i);
        *(__half2*)(out + i)     = __floats2half2_rn(v.x, v.y);
        *(__half2*)(out + i + 2) = __floats2half2_rn(v.z, v.w);
    }
}

// ---------------------------------------------------------------------------
// fp16 tensor-core GEMM: C[M,N] = A[M,K] @ W[N,K]^T + bias[N], fp32 acc.
// BM=BN=128, BK=32, 256 threads (8 warps: 4M x 2N), warp tile 32x64.
// 2-stage cp.async double buffer, ldmatrix fragments.
// SCATTER=1: writes fp16 to g_qkvh [3][B][H][S][hd]. Ain==nullptr -> g_attnh.
// ---------------------------------------------------------------------------
#define GST 40                     // smem row stride in halves (32 + 8 pad)
#define GBUF (128 * GST * 2)       // bytes per stage per matrix

template<int SCATTER>
__global__ __launch_bounds__(256)
void gemm_h(const __half* __restrict__ Ain, const __half* __restrict__ W,
            const float* __restrict__ bias, float* __restrict__ C,
            int N, int K)
{
    const __half* A = Ain ? Ain : g_attnh;

    __shared__ __half As[2][128 * GST];
    __shared__ __half Bs[2][128 * GST];

    const int tid = threadIdx.x;
    const int lane = tid & 31, warp = tid >> 5;
    const int wm = warp & 3, wn = warp >> 2;
    const int g = lane >> 2, tg = lane & 3;
    const int m0 = blockIdx.y * 128, n0 = blockIdx.x * 128;

    const unsigned sA = smem_u32(&As[0][0]);
    const unsigned sB = smem_u32(&Bs[0][0]);

    // ldmatrix per-lane address components
    const int ra = (lane & 7) + 8 * ((lane >> 3) & 1);  // A rows
    const int ka = 8 * (lane >> 4);                     // A k-offset (halves)
    const int rb = (lane & 7) + 8 * (lane >> 4);        // B rows (n)
    const int kb = 8 * ((lane >> 3) & 1);               // B k-offset

    float acc[2][8][4];
#pragma unroll
    for (int mi = 0; mi < 2; mi++)
#pragma unroll
        for (int ni = 0; ni < 8; ni++)
#pragma unroll
            for (int c = 0; c < 4; c++) acc[mi][ni][c] = 0.0f;

    const __half* aA = A + (size_t)m0 * K;
    const __half* aW = W + (size_t)n0 * K;

    auto prefetch = [&](int it, int buf) {
        const int k0 = it * 32;
#pragma unroll
        for (int i = 0; i < 2; i++) {
            const int c = tid + i * 256;
            const int row = c >> 2, q = c & 3;
            cp_async16(sA + buf * GBUF + (row * GST + q * 8) * 2,
                       aA + (size_t)row * K + k0 + q * 8);
            cp_async16(sB + buf * GBUF + (row * GST + q * 8) * 2,
                       aW + (size_t)row * K + k0 + q * 8);
        }
        cp_commit();
    };

    prefetch(0, 0);
    const int T = K / 32;

    for (int it = 0; it < T; it++) {
        const int buf = it & 1;
        cp_wait<0>();
        __syncthreads();
        if (it + 1 < T) prefetch(it + 1, buf ^ 1);

#pragma unroll
        for (int ks = 0; ks < 2; ks++) {
            unsigned af[2][4];
#pragma unroll
            for (int mi = 0; mi < 2; mi++) {
                const unsigned addr = sA + buf * GBUF +
                    ((wm * 32 + mi * 16 + ra) * GST + ks * 16 + ka) * 2;
                ldsm4(af[mi][0], af[mi][1], af[mi][2], af[mi][3], addr);
            }
            unsigned bf[8][2];
#pragma unroll
            for (int ntp = 0; ntp < 4; ntp++) {
                unsigned r0, r1, r2, r3;
                const unsigned addr = sB + buf * GBUF +
                    ((wn * 64 + ntp * 16 + rb) * GST + ks * 16 + kb) * 2;
                ldsm4(r0, r1, r2, r3, addr);
                bf[2 * ntp][0] = r0; bf[2 * ntp][1] = r1;
                bf[2 * ntp + 1][0] = r2; bf[2 * ntp + 1][1] = r3;
            }
#pragma unroll
            for (int mi = 0; mi < 2; mi++)
#pragma unroll
                for (int ni = 0; ni < 8; ni++)
                    mma16816(acc[mi][ni], af[mi], bf[ni]);
        }
    }

    // epilogue
#pragma unroll
    for (int mi = 0; mi < 2; mi++) {
#pragma unroll
        for (int half = 0; half < 2; half++) {
            const int m = m0 + wm * 32 + mi * 16 + g + half * 8;
#pragma unroll
            for (int ni = 0; ni < 8; ni++) {
                const int n = n0 + wn * 64 + ni * 8 + 2 * tg;
                const float v0 = acc[mi][ni][half * 2 + 0] + bias[n];
                const float v1 = acc[mi][ni][half * 2 + 1] + bias[n + 1];
                if (SCATTER) {
                    const int three = n >> 10;
                    const int h = (n >> 6) & (H_ - 1);
                    const int d = n & (HD_ - 1);
                    const int b = m >> 11;
                    const int s = m & (S_ - 1);
                    *(__half2*)&g_qkvh[((size_t)three * (B_ * H_) + b * H_ + h) * (S_ * HD_)
                                       + (size_t)s * HD_ + d] = __floats2half2_rn(v0, v1);
                } else {
                    *(float2*)&C[(size_t)m * N + n] = make_float2(v0, v1);
                }
            }
        }
    }
}

// ---------------------------------------------------------------------------
// fp16 tensor-core flash attention. CTA = 64 queries x 1 (b,h); 4 warps x 16 q.
// 64-key tiles, 2-stage cp.async, ldmatrix (K non-trans, V trans), P in regs.
// grid = (S/64, B*H), block = 128.
// ---------------------------------------------------------------------------
#define AST 72                     // K/V smem row stride in halves (64 + 8)
#define ABUF (64 * AST * 2)        // bytes per stage per matrix

__global__ __launch_bounds__(128)
void attn_h()
{
    const int bh = blockIdx.y;
    const int q0 = blockIdx.x * 64;
    const int tid = threadIdx.x;
    const int warp = tid >> 5, lane = tid & 31;
    const int g = lane >> 2, tg = lane & 3;

    const __half* Qp = g_qkvh + (size_t)bh * (S_ * HD_);
    const __half* Kp = g_qkvh + (size_t)(B_ * H_ + bh) * (S_ * HD_);
    const __half* Vp = g_qkvh + (size_t)(2 * B_ * H_ + bh) * (S_ * HD_);

    __shared__ __half Ks[2][64 * AST];
    __shared__ __half Vs[2][64 * AST];
    const unsigned sK = smem_u32(&Ks[0][0]);
    const unsigned sV = smem_u32(&Vs[0][0]);

    // Q fragments: m16 x k64 = 4 k16-steps
    unsigned qa[4][4];
    {
        const __half* Qr0 = Qp + (size_t)(q0 + warp * 16 + g) * HD_;
        const __half* Qr1 = Qp + (size_t)(q0 + warp * 16 + g + 8) * HD_;
#pragma unroll
        for (int ks = 0; ks < 4; ks++) {
            qa[ks][0] = *(const unsigned*)(Qr0 + ks * 16 + 2 * tg);
            qa[ks][1] = *(const unsigned*)(Qr1 + ks * 16 + 2 * tg);
            qa[ks][2] = *(const unsigned*)(Qr0 + ks * 16 + 8 + 2 * tg);
            qa[ks][3] = *(const unsigned*)(Qr1 + ks * 16 + 8 + 2 * tg);
        }
    }

    // ldmatrix lane address components
    const int rkb = (lane & 7) + 8 * (lane >> 4);        // K: rows = keys
    const int kkb = 8 * ((lane >> 3) & 1);               // K: hd offset
    const int rvb = (lane & 7) + 8 * ((lane >> 3) & 1);  // V(trans): rows = keys
    const int kvb = 8 * (lane >> 4);                     // V: hd offset

    float o[8][4];
#pragma unroll
    for (int ni = 0; ni < 8; ni++)
#pragma unroll
        for (int c = 0; c < 4; c++) o[ni][c] = 0.0f;
    float m0v = -3.0e38f, m1v = -3.0e38f, l0 = 0.0f, l1 = 0.0f;

    auto prefetch = [&](int it, int buf) {
        const int kt = it * 64;
#pragma unroll
        for (int i = 0; i < 4; i++) {
            const int c = tid + i * 128;
            const int row = c >> 3, q = c & 7;
            cp_async16(sK + buf * ABUF + (row * AST + q * 8) * 2,
                       Kp + (size_t)(kt + row) * HD_ + q * 8);
            cp_async16(sV + buf * ABUF + (row * AST + q * 8) * 2,
                       Vp + (size_t)(kt + row) * HD_ + q * 8);
        }
        cp_commit();
    };

    prefetch(0, 0);

    for (int it = 0; it < S_ / 64; it++) {
        const int buf = it & 1;
        cp_wait<0>();
        __syncthreads();
        if (it + 1 < S_ / 64) prefetch(it + 1, buf ^ 1);

        // S = Q K^T : warp m16 x n64, k=64
        float sc[8][4];
#pragma unroll
        for (int ni = 0; ni < 8; ni++)
#pragma unroll
            for (int c = 0; c < 4; c++) sc[ni][c] = 0.0f;
#pragma unroll
        for (int ks = 0; ks < 4; ks++) {
#pragma unroll
            for (int ntp = 0; ntp < 4; ntp++) {
                unsigned r0, r1, r2, r3;
                const unsigned addr = sK + buf * ABUF +
                    ((ntp * 16 + rkb) * AST + ks * 16 + kkb) * 2;
                ldsm4(r0, r1, r2, r3, addr);
                unsigned b0[2] = {r0, r1}, b1[2] = {r2, r3};
                mma16816(sc[2 * ntp], qa[ks], b0);
                mma16816(sc[2 * ntp + 1], qa[ks], b1);
            }
        }
#pragma unroll
        for (int ni = 0; ni < 8; ni++)
#pragma unroll
            for (int c = 0; c < 4; c++) sc[ni][c] *= 0.125f;

        // online softmax: rows g (c0,c1) and g+8 (c2,c3); 4 lanes/row
        float mt0 = -3.0e38f, mt1 = -3.0e38f;
#pragma unroll
        for (int ni = 0; ni < 8; ni++) {
            mt0 = fmaxf(mt0, fmaxf(sc[ni][0], sc[ni][1]));
            mt1 = fmaxf(mt1, fmaxf(sc[ni][2], sc[ni][3]));
        }
        mt0 = fmaxf(mt0, __shfl_xor_sync(0xffffffffu, mt0, 1));
        mt0 = fmaxf(mt0, __shfl_xor_sync(0xffffffffu, mt0, 2));
        mt1 = fmaxf(mt1, __shfl_xor_sync(0xffffffffu, mt1, 1));
        mt1 = fmaxf(mt1, __shfl_xor_sync(0xffffffffu, mt1, 2));

        const float mn0 = fmaxf(m0v, mt0), mn1 = fmaxf(m1v, mt1);
        const float a0 = __expf(m0v - mn0), a1 = __expf(m1v - mn1);
        m0v = mn0; m1v = mn1;
        l0 *= a0; l1 *= a1;
#pragma unroll
        for (int ni = 0; ni < 8; ni++) {
            o[ni][0] *= a0; o[ni][1] *= a0;
            o[ni][2] *= a1; o[ni][3] *= a1;
        }

        unsigned ph[8][2];
        float s0 = 0.0f, s1 = 0.0f;
#pragma unroll
        for (int ni = 0; ni < 8; ni++) {
            const float p0 = __expf(sc[ni][0] - mn0);
            const float p1 = __expf(sc[ni][1] - mn0);
            const float p2 = __expf(sc[ni][2] - mn1);
            const float p3 = __expf(sc[ni][3] - mn1);
            s0 += p0 + p1; s1 += p2 + p3;
            __half2 h0 = __floats2half2_rn(p0, p1);
            __half2 h1 = __floats2half2_rn(p2, p3);
            ph[ni][0] = *(unsigned*)&h0;
            ph[ni][1] = *(unsigned*)&h1;
        }
        s0 += __shfl_xor_sync(0xffffffffu, s0, 1);
        s0 += __shfl_xor_sync(0xffffffffu, s0, 2);
        s1 += __shfl_xor_sync(0xffffffffu, s1, 1);
        s1 += __shfl_xor_sync(0xffffffffu, s1, 2);
        l0 += s0; l1 += s1;

        // O += P V : A-frags directly from S c-frag pairs (no smem round-trip)
#pragma unroll
        for (int ks = 0; ks < 4; ks++) {
            unsigned pa[4];
            pa[0] = ph[2 * ks][0];
            pa[1] = ph[2 * ks][1];
            pa[2] = ph[2 * ks + 1][0];
            pa[3] = ph[2 * ks + 1][1];
#pragma unroll
            for (int ntp = 0; ntp < 4; ntp++) {
                unsigned r0, r1, r2, r3;
                const unsigned addr = sV + buf * ABUF +
                    ((ks * 16 + rvb) * AST + ntp * 16 + kvb) * 2;
                ldsm4t(r0, r1, r2, r3, addr);
                unsigned b0[2] = {r0, r1}, b1[2] = {r2, r3};
                mma16816(o[2 * ntp], pa, b0);
                mma16816(o[2 * ntp + 1], pa, b1);
            }
        }
    }

    // epilogue: normalize, write fp16 to g_attnh [B*S][D]
    const int b = bh >> 4, h = bh & (H_ - 1);
    const float i0 = 1.0f / l0, i1 = 1.0f / l1;
    __half* O0 = g_attnh + (size_t)(b * S_ + q0 + warp * 16 + g) * D_ + h * HD_;
    __half* O1 = g_attnh + (size_t)(b * S_ + q0 + warp * 16 + g + 8) * D_ + h * HD_;
#pragma unroll
    for (int ni = 0; ni < 8; ni++) {
        const int c = ni * 8 + 2 * tg;
        *(__half2*)(O0 + c) = __floats2half2_rn(o[ni][0] * i0, o[ni][1] * i0);
        *(__half2*)(O1 + c) = __floats2half2_rn(o[ni][2] * i1, o[ni][3] * i1);
    }
}

// ---------------------------------------------------------------------------
extern "C" void kernel_launch(void* const* d_in, const int* in_sizes, int n_in,
                              void* d_out, int out_size)
{
    const float* x      = (const float*)d_in[0];
    const float* w_qkv  = (const float*)d_in[1];
    const float* b_qkv  = (const float*)d_in[2];
    const float* w_proj = (const float*)d_in[3];
    const float* b_proj = (const float*)d_in[4];
    float* out = (float*)d_out;

    // 0) fp32 -> fp16 converts
    __half *xh, *wqkvh, *wprojh;
    cudaGetSymbolAddress((void**)&xh,     g_xh);
    cudaGetSymbolAddress((void**)&wqkvh,  g_wqkvh);
    cudaGetSymbolAddress((void**)&wprojh, g_wprojh);
    cvt_kernel<<<(M_ * D_) / 4 / 256, 256>>>(x, xh, M_ * D_);
    cvt_kernel<<<(3 * D_ * D_) / 4 / 256, 256>>>(w_qkv, wqkvh, 3 * D_ * D_);
    cvt_kernel<<<(D_ * D_) / 4 / 256, 256>>>(w_proj, wprojh, D_ * D_);

    // 1) QKV projection -> g_qkvh [3,B,H,S,hd] (fp16)
    dim3 g1((3 * D_) / 128, M_ / 128);   // (24, 32)
    gemm_h<1><<<g1, 256>>>(xh, wqkvh, b_qkv, nullptr, 3 * D_, D_);

    // 2) attention -> g_attnh [B,S,D] (fp16)
    attn_h<<<dim3(S_ / 64, B_ * H_), 128>>>();

    // 3) output projection -> d_out (fp32)
    dim3 g2(D_ / 128, M_ / 128);         // (8, 32)
    gemm_h<0><<<g2, 256>>>(nullptr, wprojh, b_proj, out, D_, D_);
}